// round 1
// baseline (speedup 1.0000x reference)
#include <cuda_runtime.h>

#define C_CLASS 32
#define S_SUP   16
#define D_DIM   1024
#define QB      8           // queries per CTA
#define THREADS 256

// smem: cs[16][1024] (scaled support), qt[8][1024], scores double buffer
#define SMEM_FLOATS (S_SUP*D_DIM + QB*D_DIM + 64)
#define SMEM_BYTES  (SMEM_FLOATS * 4)

__device__ __forceinline__ float fex2(float x) {
    float y; asm("ex2.approx.f32 %0, %1;" : "=f"(y) : "f"(x)); return y;
}
__device__ __forceinline__ float frcp(float x) {
    float y; asm("rcp.approx.f32 %0, %1;" : "=f"(y) : "f"(x)); return y;
}

// tanh(p) where z = SCALE*p already computed (SCALE = -2*log2e):
// t = 2^z = e^{-2p};  tanh(p) = (1-t)/(1+t) = r - t*r,  r = 1/(1+t)
#define TANH_ACC(acc, sv, qv) do {                      \
    float z_ = fminf((sv) * (qv), 30.0f);               \
    float t_ = fex2(z_);                                \
    float r_ = frcp(1.0f + t_);                         \
    (acc) += r_;                                        \
    (acc) = fmaf(-t_, r_, (acc));                       \
} while (0)

__global__ __launch_bounds__(THREADS, 2)
void instance_attention_kernel(const float* __restrict__ data,
                               float* __restrict__ out)
{
    extern __shared__ float sm[];
    float* cs     = sm;                       // scaled support tile [16][1024]
    float* qt     = sm + S_SUP * D_DIM;       // query tile [8][1024]
    float* scores = qt + QB * D_DIM;          // [2][16] double buffer

    const int c    = blockIdx.y;
    const int qb   = blockIdx.x;
    const int tid  = threadIdx.x;
    const int w    = tid >> 5;
    const int lane = tid & 31;

    const float SCALE     = -2.885390081777927f;    // -2*log2(e)
    const float INV_SCALE = -0.34657359027997264f;  // 1/SCALE = -ln2/2
    const float LOG2E     =  1.4426950408889634f;

    // ---- load support tile (pre-scaled) and query tile into smem ----
    const float4* supg = (const float4*)(data + (size_t)(c * S_SUP) * D_DIM);
    float4* cs4 = (float4*)cs;
    #pragma unroll
    for (int i = tid; i < S_SUP * D_DIM / 4; i += THREADS) {
        float4 v = supg[i];
        v.x *= SCALE; v.y *= SCALE; v.z *= SCALE; v.w *= SCALE;
        cs4[i] = v;
    }
    const float4* qg = (const float4*)(data + (size_t)(C_CLASS * S_SUP + qb * QB) * D_DIM);
    float4* qt4 = (float4*)qt;
    #pragma unroll
    for (int i = tid; i < QB * D_DIM / 4; i += THREADS) {
        qt4[i] = qg[i];
    }
    __syncthreads();

    for (int ql = 0; ql < QB; ++ql) {
        // ---- scores: warp w handles support rows s=w and s=w+8 ----
        const float4* qrow = (const float4*)(qt + ql * D_DIM);
        const float4* r0   = (const float4*)(cs + (size_t)w * D_DIM);
        const float4* r1   = (const float4*)(cs + (size_t)(w + 8) * D_DIM);
        float a0 = 0.0f, a1 = 0.0f;
        #pragma unroll
        for (int it = 0; it < D_DIM / 128; ++it) {
            int idx = it * 32 + lane;
            float4 qv = qrow[idx];
            float4 s0 = r0[idx];
            float4 s1 = r1[idx];
            TANH_ACC(a0, s0.x, qv.x);
            TANH_ACC(a0, s0.y, qv.y);
            TANH_ACC(a0, s0.z, qv.z);
            TANH_ACC(a0, s0.w, qv.w);
            TANH_ACC(a1, s1.x, qv.x);
            TANH_ACC(a1, s1.y, qv.y);
            TANH_ACC(a1, s1.z, qv.z);
            TANH_ACC(a1, s1.w, qv.w);
        }
        #pragma unroll
        for (int off = 16; off; off >>= 1) {
            a0 += __shfl_xor_sync(0xffffffffu, a0, off);
            a1 += __shfl_xor_sync(0xffffffffu, a1, off);
        }
        float* sb = scores + (ql & 1) * 16;
        if (lane == 0) { sb[w] = a0; sb[w + 8] = a1; }
        __syncthreads();

        // ---- softmax (per-thread redundant over 16 values) ----
        float e[16];
        float m = -1e30f;
        #pragma unroll
        for (int s = 0; s < 16; ++s) { e[s] = sb[s]; m = fmaxf(m, e[s]); }
        float ssum = 0.0f;
        #pragma unroll
        for (int s = 0; s < 16; ++s) { e[s] = fex2((e[s] - m) * LOG2E); ssum += e[s]; }
        float f = frcp(ssum) * INV_SCALE;   // undo SCALE baked into cs

        // ---- proto: thread tid handles 4 output columns ----
        float4 o = make_float4(0.f, 0.f, 0.f, 0.f);
        #pragma unroll
        for (int s = 0; s < 16; ++s) {
            float4 v = cs4[s * (D_DIM / 4) + tid];
            o.x = fmaf(e[s], v.x, o.x);
            o.y = fmaf(e[s], v.y, o.y);
            o.z = fmaf(e[s], v.z, o.z);
            o.w = fmaf(e[s], v.w, o.w);
        }
        o.x *= f; o.y *= f; o.z *= f; o.w *= f;

        const int qglob = qb * QB + ql;
        float4* og = (float4*)(out + ((size_t)qglob * C_CLASS + c) * D_DIM);
        og[tid] = o;
        // no second barrier needed: scores is double-buffered, cs/qt read-only
    }
}

extern "C" void kernel_launch(void* const* d_in, const int* in_sizes, int n_in,
                              void* d_out, int out_size)
{
    (void)in_sizes; (void)n_in; (void)out_size;
    const float* data = (const float*)d_in[0];
    float* out = (float*)d_out;

    cudaFuncSetAttribute(instance_attention_kernel,
                         cudaFuncAttributeMaxDynamicSharedMemorySize, SMEM_BYTES);

    dim3 grid(512 / QB, C_CLASS);   // (64 query-blocks, 32 classes)
    instance_attention_kernel<<<grid, THREADS, SMEM_BYTES>>>(data, out);
}